// round 10
// baseline (speedup 1.0000x reference)
#include <cuda_runtime.h>
#include <cstdint>

#define B_   2
#define T_   4096
#define D_   512
#define H_   8
#define HD_  64
#define M_   (B_ * T_)
#define N3_  (3 * D_)

__device__ float g_qkv[M_ * N3_];
__device__ float g_att[M_ * D_];

// ---------------------------------------------------------------------------
// tf32 helpers
// ---------------------------------------------------------------------------
__device__ __forceinline__ unsigned f2tf(float x) {
    unsigned r;
    asm("cvt.rna.tf32.f32 %0, %1;" : "=r"(r) : "f"(x));
    return r;
}
__device__ __forceinline__ float tf2f(float x) { return __uint_as_float(f2tf(x)); }

__device__ __forceinline__ float ex2(float x) {
    float r;
    asm("ex2.approx.ftz.f32 %0, %1;" : "=f"(r) : "f"(x));
    return r;
}

__device__ __forceinline__ void mma_tf32(float d[4], const unsigned a[4],
                                         const unsigned b[2]) {
    asm volatile(
        "mma.sync.aligned.m16n8k8.row.col.f32.tf32.tf32.f32 "
        "{%0,%1,%2,%3}, {%4,%5,%6,%7}, {%8,%9}, {%0,%1,%2,%3};\n"
        : "+f"(d[0]), "+f"(d[1]), "+f"(d[2]), "+f"(d[3])
        : "r"(a[0]), "r"(a[1]), "r"(a[2]), "r"(a[3]), "r"(b[0]), "r"(b[1]));
}

// ---------------------------------------------------------------------------
// NT GEMM with tf32 mma — EXACT R2/R5/R6 version (107.7us qkv, regs 62).
// ---------------------------------------------------------------------------
__device__ __forceinline__ void gemm_nt_mma(const float* __restrict__ A,
                                            const float* __restrict__ Bm,
                                            float* __restrict__ C,
                                            int N, int K) {
    __shared__ float As[128 * 36];
    __shared__ float Bs[64 * 36];

    const int tid = threadIdx.x;
    const int w = tid >> 5;
    const int lane = tid & 31;
    const int gid = lane >> 2;
    const int tig = lane & 3;
    const int wm = w >> 1;
    const int wn = w & 1;

    const int m0 = blockIdx.y * 128;
    const int n0 = blockIdx.x * 64;

    const int lr = tid >> 3;
    const int lc = (tid & 7) * 4;

    float acc[2][4][4] = {};

    for (int k0 = 0; k0 < K; k0 += 32) {
        float4 a4[4], b4[2];
#pragma unroll
        for (int i = 0; i < 4; ++i)
            a4[i] = *reinterpret_cast<const float4*>(
                A + (size_t)(m0 + lr + 32 * i) * K + k0 + lc);
#pragma unroll
        for (int i = 0; i < 2; ++i)
            b4[i] = *reinterpret_cast<const float4*>(
                Bm + (size_t)(n0 + lr + 32 * i) * K + k0 + lc);
        __syncthreads();
#pragma unroll
        for (int i = 0; i < 4; ++i) {
            float* p = As + (lr + 32 * i) * 36 + lc;
            p[0] = tf2f(a4[i].x); p[1] = tf2f(a4[i].y);
            p[2] = tf2f(a4[i].z); p[3] = tf2f(a4[i].w);
        }
#pragma unroll
        for (int i = 0; i < 2; ++i) {
            float* p = Bs + (lr + 32 * i) * 36 + lc;
            p[0] = tf2f(b4[i].x); p[1] = tf2f(b4[i].y);
            p[2] = tf2f(b4[i].z); p[3] = tf2f(b4[i].w);
        }
        __syncthreads();

#pragma unroll
        for (int ks = 0; ks < 4; ++ks) {
            unsigned aa[2][4], bb[4][2];
#pragma unroll
            for (int mt = 0; mt < 2; ++mt) {
                const float* p = As + (wm * 32 + mt * 16 + gid) * 36 + ks * 8 + tig;
                aa[mt][0] = __float_as_uint(p[0]);
                aa[mt][1] = __float_as_uint(p[8 * 36]);
                aa[mt][2] = __float_as_uint(p[4]);
                aa[mt][3] = __float_as_uint(p[8 * 36 + 4]);
            }
#pragma unroll
            for (int nt = 0; nt < 4; ++nt) {
                const float* p = Bs + (wn * 32 + nt * 8 + gid) * 36 + ks * 8 + tig;
                bb[nt][0] = __float_as_uint(p[0]);
                bb[nt][1] = __float_as_uint(p[4]);
            }
#pragma unroll
            for (int mt = 0; mt < 2; ++mt)
#pragma unroll
                for (int nt = 0; nt < 4; ++nt)
                    mma_tf32(acc[mt][nt], aa[mt], bb[nt]);
        }
    }

#pragma unroll
    for (int mt = 0; mt < 2; ++mt) {
        const int r0 = m0 + wm * 32 + mt * 16 + gid;
#pragma unroll
        for (int nt = 0; nt < 4; ++nt) {
            const int c = n0 + wn * 32 + nt * 8 + 2 * tig;
            *reinterpret_cast<float2*>(C + (size_t)r0 * N + c) =
                make_float2(acc[mt][nt][0], acc[mt][nt][1]);
            *reinterpret_cast<float2*>(C + (size_t)(r0 + 8) * N + c) =
                make_float2(acc[mt][nt][2], acc[mt][nt][3]);
        }
    }
}

__global__ void __launch_bounds__(256)
gemm_qkv_kernel(const float* __restrict__ x, const float* __restrict__ w) {
    gemm_nt_mma(x, w, g_qkv, N3_, D_);
}

__global__ void __launch_bounds__(256)
gemm_out_kernel(const float* __restrict__ w, float* __restrict__ out) {
    gemm_nt_mma(g_att, w, out, D_, D_);
}

// ---------------------------------------------------------------------------
// Flash attention (causal), tf32 mma — R6 numerics & 32-rows/warp tile,
// repackaged as 128-thread blocks (4 warps) so 2 CTAs/SM co-reside:
//   - smem/MMA ratio ~0.63 (MMA-bound, not crossbar-bound)
//   - 256 regs/thread budget at occ 2 (no spills)
//   - co-resident CTA hides softmax/LDG latency
// SMEM: Qs[128][72] + Ks[64][72] + Vs[64][72] = 73728 B.
// Grid = 512 blocks (16 bh x 32 q-tiles), heavy tiles first.
// ---------------------------------------------------------------------------
#define LDQ 72
#define FLASH_SMEM ((128 * LDQ + 64 * LDQ + 64 * LDQ) * 4)
#define QSCALE 0.180336879f   /* 0.125 * log2(e) */

__global__ void __launch_bounds__(128, 2) flash_mma_kernel() {
    extern __shared__ float sm[];
    float* Qs = sm;                        // [128][LDQ] interleaved
    float* Ks = sm + 128 * LDQ;            // [64][LDQ]  interleaved
    float* Vs = sm + 192 * LDQ;            // [64][LDQ]  plain

    const int tid = threadIdx.x;
    const int w = tid >> 5;                // 0..3
    const int lane = tid & 31;
    const int gid = lane >> 2;
    const int tig = lane & 3;

    const int qt = (int)gridDim.y - 1 - (int)blockIdx.y;   // heavy tiles first
    const int q0 = qt * 128;
    const int bh = blockIdx.x;
    const int b = bh >> 3;
    const int h = bh & 7;

    const float* qptr = g_qkv + (size_t)b * T_ * N3_ + h * HD_;
    const float* kptr = qptr + D_;
    const float* vptr = qptr + 2 * D_;

    const int lr = tid >> 4;          // 0..7
    const int c = tid & 15;           // d-chunk
    const int pbase = (c & 1) + (c >> 1) * 8;

    // ---- stage Q (scaled into log2 domain, tf32, interleaved) ----
#pragma unroll
    for (int i = 0; i < 16; ++i) {
        const int rr = lr + 8 * i;
        const float4 v = *reinterpret_cast<const float4*>(
            qptr + (size_t)(q0 + rr) * N3_ + c * 4);
        float* p = Qs + rr * LDQ + pbase;
        p[0] = tf2f(v.x * QSCALE); p[2] = tf2f(v.y * QSCALE);
        p[4] = tf2f(v.z * QSCALE); p[6] = tf2f(v.w * QSCALE);
    }

    // ---- preload first K/V tile (8 rows per thread-pass) ----
    float4 kreg[8], vreg[8];
#pragma unroll
    for (int i = 0; i < 8; ++i) {
        kreg[i] = *reinterpret_cast<const float4*>(kptr + (size_t)(lr + 8 * i) * N3_ + c * 4);
        vreg[i] = *reinterpret_cast<const float4*>(vptr + (size_t)(lr + 8 * i) * N3_ + c * 4);
    }

    float oc[2][8][4] = {};
    float li[2][2] = {};

    const int rowlo = q0 + w * 32;       // warp's lowest q row
    const int niter = 2 * (qt + 1);

    const unsigned shbase = lane & 0x1Cu;
    const int h1 = tig >> 1;
    const bool odd = tig & 1;

    for (int it = 0; it < niter; ++it) {
        const int j0 = it * 64;
        __syncthreads();
        // store K interleaved, V plain
#pragma unroll
        for (int i = 0; i < 8; ++i) {
            const int rr = lr + 8 * i;
            float* pk = Ks + rr * LDQ + pbase;
            pk[0] = tf2f(kreg[i].x); pk[2] = tf2f(kreg[i].y);
            pk[4] = tf2f(kreg[i].z); pk[6] = tf2f(kreg[i].w);
            *reinterpret_cast<float4*>(Vs + rr * LDQ + c * 4) =
                make_float4(tf2f(vreg[i].x), tf2f(vreg[i].y),
                            tf2f(vreg[i].z), tf2f(vreg[i].w));
        }
        __syncthreads();

        if (it + 1 < niter) {
            const int jn = j0 + 64;
#pragma unroll
            for (int i = 0; i < 8; ++i) {
                kreg[i] = *reinterpret_cast<const float4*>(
                    kptr + (size_t)(jn + lr + 8 * i) * N3_ + c * 4);
                vreg[i] = *reinterpret_cast<const float4*>(
                    vptr + (size_t)(jn + lr + 8 * i) * N3_ + c * 4);
            }
        }

        if (j0 > rowlo + 31) continue;   // warp fully masked this iter

        // ---- S = Q K^T  (both 16-row halves share each K fragment) ----
        float sc[2][8][4] = {};
#pragma unroll
        for (int ks = 0; ks < 8; ++ks) {
            unsigned qa[2][4];
#pragma unroll
            for (int mt = 0; mt < 2; ++mt) {
                const float* p = Qs + (w * 32 + mt * 16 + gid) * LDQ + ks * 8 + 2 * tig;
                const float2 f0 = *reinterpret_cast<const float2*>(p);
                const float2 f1 = *reinterpret_cast<const float2*>(p + 8 * LDQ);
                qa[mt][0] = __float_as_uint(f0.x); qa[mt][2] = __float_as_uint(f0.y);
                qa[mt][1] = __float_as_uint(f1.x); qa[mt][3] = __float_as_uint(f1.y);
            }
#pragma unroll
            for (int nt = 0; nt < 8; ++nt) {
                unsigned kb[2];
                const float2 f = *reinterpret_cast<const float2*>(
                    Ks + (nt * 8 + gid) * LDQ + ks * 8 + 2 * tig);
                kb[0] = __float_as_uint(f.x);
                kb[1] = __float_as_uint(f.y);
                mma_tf32(sc[0][nt], qa[0], kb);
                mma_tf32(sc[1][nt], qa[1], kb);
            }
        }

        // ---- causal mask ----
#pragma unroll
        for (int mt = 0; mt < 2; ++mt) {
            const int rbase = rowlo + mt * 16;
            if (j0 + 63 > rbase) {
                const int r0 = rbase + gid, r1 = rbase + gid + 8;
#pragma unroll
                for (int nt = 0; nt < 8; ++nt) {
                    const int cc = j0 + nt * 8 + 2 * tig;
                    if (cc > r0)     sc[mt][nt][0] = -1e30f;
                    if (cc + 1 > r0) sc[mt][nt][1] = -1e30f;
                    if (cc > r1)     sc[mt][nt][2] = -1e30f;
                    if (cc + 1 > r1) sc[mt][nt][3] = -1e30f;
                }
            }
        }

        // ---- exp2 (no max subtraction) + per-lane row sums ----
#pragma unroll
        for (int mt = 0; mt < 2; ++mt) {
            float s0 = 0.0f, s1 = 0.0f;
#pragma unroll
            for (int nt = 0; nt < 8; ++nt) {
                sc[mt][nt][0] = ex2(sc[mt][nt][0]);
                sc[mt][nt][1] = ex2(sc[mt][nt][1]);
                sc[mt][nt][2] = ex2(sc[mt][nt][2]);
                sc[mt][nt][3] = ex2(sc[mt][nt][3]);
                s0 += sc[mt][nt][0] + sc[mt][nt][1];
                s1 += sc[mt][nt][2] + sc[mt][nt][3];
            }
            li[mt][0] += s0;
            li[mt][1] += s1;
        }

        // ---- P: C-layout -> A-layout via shuffles ----
        unsigned pa[2][8][4];
        const int src0 = shbase + h1;
        const int src2 = shbase + h1 + 2;
#pragma unroll
        for (int mt = 0; mt < 2; ++mt)
#pragma unroll
            for (int nt = 0; nt < 8; ++nt) {
                const float c0 = sc[mt][nt][0], c1 = sc[mt][nt][1];
                const float c2 = sc[mt][nt][2], c3 = sc[mt][nt][3];
                const float u0 = __shfl_sync(0xffffffffu, c0, src0);
                const float u1 = __shfl_sync(0xffffffffu, c1, src0);
                const float u2 = __shfl_sync(0xffffffffu, c2, src0);
                const float u3 = __shfl_sync(0xffffffffu, c3, src0);
                const float v0 = __shfl_sync(0xffffffffu, c0, src2);
                const float v1 = __shfl_sync(0xffffffffu, c1, src2);
                const float v2 = __shfl_sync(0xffffffffu, c2, src2);
                const float v3 = __shfl_sync(0xffffffffu, c3, src2);
                pa[mt][nt][0] = f2tf(odd ? u1 : u0);
                pa[mt][nt][1] = f2tf(odd ? u3 : u2);
                pa[mt][nt][2] = f2tf(odd ? v1 : v0);
                pa[mt][nt][3] = f2tf(odd ? v3 : v2);
            }

        // ---- O += P V ----
#pragma unroll
        for (int dt = 0; dt < 8; ++dt) {
#pragma unroll
            for (int ks = 0; ks < 8; ++ks) {
                unsigned vb[2];
                vb[0] = __float_as_uint(Vs[(ks * 8 + tig) * LDQ + dt * 8 + gid]);
                vb[1] = __float_as_uint(Vs[(ks * 8 + tig + 4) * LDQ + dt * 8 + gid]);
                mma_tf32(oc[0][dt], pa[0][ks], vb);
                mma_tf32(oc[1][dt], pa[1][ks], vb);
            }
        }
    }

    // ---- epilogue: quad-reduce row sums, normalize, store ----
#pragma unroll
    for (int mt = 0; mt < 2; ++mt) {
        float s0 = li[mt][0], s1 = li[mt][1];
        s0 += __shfl_xor_sync(0xffffffffu, s0, 1);
        s0 += __shfl_xor_sync(0xffffffffu, s0, 2);
        s1 += __shfl_xor_sync(0xffffffffu, s1, 1);
        s1 += __shfl_xor_sync(0xffffffffu, s1, 2);
        const float inv0 = 1.0f / s0;
        const float inv1 = 1.0f / s1;
        const int r0 = q0 + w * 32 + mt * 16 + gid;
        float* out0 = g_att + ((size_t)(b * T_ + r0)) * D_ + h * HD_;
        float* out1 = g_att + ((size_t)(b * T_ + r0 + 8)) * D_ + h * HD_;
#pragma unroll
        for (int dt = 0; dt < 8; ++dt) {
            const int cc = dt * 8 + 2 * tig;
            *reinterpret_cast<float2*>(out0 + cc) =
                make_float2(oc[mt][dt][0] * inv0, oc[mt][dt][1] * inv0);
            *reinterpret_cast<float2*>(out1 + cc) =
                make_float2(oc[mt][dt][2] * inv1, oc[mt][dt][3] * inv1);
        }
    }
}

// ---------------------------------------------------------------------------
extern "C" void kernel_launch(void* const* d_in, const int* in_sizes, int n_in,
                              void* d_out, int out_size) {
    const float* x = nullptr;
    const float* w_qkv = nullptr;
    const float* w_out = nullptr;
    for (int i = 0; i < n_in; ++i) {
        if (in_sizes[i] == M_ * D_)       x = (const float*)d_in[i];
        else if (in_sizes[i] == N3_ * D_) w_qkv = (const float*)d_in[i];
        else if (in_sizes[i] == D_ * D_)  w_out = (const float*)d_in[i];
    }
    float* out = (float*)d_out;

    static bool attr_set = false;
    if (!attr_set) {
        cudaFuncSetAttribute(flash_mma_kernel,
                             cudaFuncAttributeMaxDynamicSharedMemorySize,
                             FLASH_SMEM);
        attr_set = true;
    }

    gemm_qkv_kernel<<<dim3(N3_ / 64, M_ / 128), 256>>>(x, w_qkv);
    // 512 blocks (16 bh x 32 q-tiles), 128 threads, 2 CTAs/SM
    flash_mma_kernel<<<dim3(B_ * H_, T_ / 128), 128, FLASH_SMEM>>>();
    gemm_out_kernel<<<dim3(D_ / 64, M_ / 128), 256>>>(w_out, out);
}

// round 11
// speedup vs baseline: 1.6601x; 1.6601x over previous
#include <cuda_runtime.h>
#include <cuda_fp16.h>
#include <cstdint>

#define B_   2
#define T_   4096
#define D_   512
#define H_   8
#define HD_  64
#define M_   (B_ * T_)
#define N3_  (3 * D_)

__device__ float g_qkv[M_ * N3_];
__device__ float g_att[M_ * D_];

// ---------------------------------------------------------------------------
// helpers
// ---------------------------------------------------------------------------
__device__ __forceinline__ unsigned cvt_h2(float lo, float hi) {
    unsigned r;
    asm("cvt.rn.f16x2.f32 %0, %1, %2;" : "=r"(r) : "f"(hi), "f"(lo));
    return r;
}
__device__ __forceinline__ float ex2(float x) {
    float r;
    asm("ex2.approx.ftz.f32 %0, %1;" : "=f"(r) : "f"(x));
    return r;
}
__device__ __forceinline__ void mma_f16(float d[4], const unsigned a[4],
                                        const unsigned b[2]) {
    asm volatile(
        "mma.sync.aligned.m16n8k16.row.col.f32.f16.f16.f32 "
        "{%0,%1,%2,%3}, {%4,%5,%6,%7}, {%8,%9}, {%0,%1,%2,%3};\n"
        : "+f"(d[0]), "+f"(d[1]), "+f"(d[2]), "+f"(d[3])
        : "r"(a[0]), "r"(a[1]), "r"(a[2]), "r"(a[3]), "r"(b[0]), "r"(b[1]));
}
__device__ __forceinline__ uint32_t smem_u32(const void* p) {
    uint32_t a;
    asm("{ .reg .u64 t; cvta.to.shared.u64 t, %1; cvt.u32.u64 %0, t; }"
        : "=r"(a) : "l"(p));
    return a;
}

// 16-halfs chunk interleave: within chunk ks, half2 slot ks*8+2t   = (d 16ks+2t, +1)
//                                            half2 slot ks*8+2t+1 = (d 16ks+2t+8, +9)
// staging: float4 at d=4c -> slots pb, pb+2 with pb = (c>>2)*8 + 4*(c&1) + ((c&3)>>1)
#define PBASE(c) (((c) >> 2) * 8 + 4 * ((c) & 1) + (((c) & 3) >> 1))

// ---------------------------------------------------------------------------
// NT GEMM, f16 mma m16n8k16: C[m,n] = sum_k A[m,k]*B[n,k]
// BM=128, BN=64, BK=32, 8 warps (4x2), warp tile 32x32 (R2 structure).
// SMEM rows: 16 half2 data, stride 24 half2 (96B) -> conflict-free frag LDS.64.
// ---------------------------------------------------------------------------
__device__ __forceinline__ void gemm_nt_f16(const float* __restrict__ A,
                                            const float* __restrict__ Bm,
                                            float* __restrict__ C,
                                            int N, int K) {
    __shared__ unsigned As[128 * 24];
    __shared__ unsigned Bs[64 * 24];

    const int tid = threadIdx.x;
    const int w = tid >> 5;
    const int lane = tid & 31;
    const int gid = lane >> 2;
    const int tig = lane & 3;
    const int wm = w >> 1;
    const int wn = w & 1;

    const int m0 = blockIdx.y * 128;
    const int n0 = blockIdx.x * 64;

    const int lr = tid >> 3;          // 0..31
    const int c = tid & 7;            // k-chunk of 4 floats
    const int pb = PBASE(c);

    float acc[2][4][4] = {};

    for (int k0 = 0; k0 < K; k0 += 32) {
        float4 a4[4], b4[2];
#pragma unroll
        for (int i = 0; i < 4; ++i)
            a4[i] = *reinterpret_cast<const float4*>(
                A + (size_t)(m0 + lr + 32 * i) * K + k0 + c * 4);
#pragma unroll
        for (int i = 0; i < 2; ++i)
            b4[i] = *reinterpret_cast<const float4*>(
                Bm + (size_t)(n0 + lr + 32 * i) * K + k0 + c * 4);
        __syncthreads();
#pragma unroll
        for (int i = 0; i < 4; ++i) {
            unsigned* p = As + (lr + 32 * i) * 24 + pb;
            p[0] = cvt_h2(a4[i].x, a4[i].y);
            p[2] = cvt_h2(a4[i].z, a4[i].w);
        }
#pragma unroll
        for (int i = 0; i < 2; ++i) {
            unsigned* p = Bs + (lr + 32 * i) * 24 + pb;
            p[0] = cvt_h2(b4[i].x, b4[i].y);
            p[2] = cvt_h2(b4[i].z, b4[i].w);
        }
        __syncthreads();

#pragma unroll
        for (int ks = 0; ks < 2; ++ks) {
            unsigned aa[2][4], bb[4][2];
#pragma unroll
            for (int mt = 0; mt < 2; ++mt) {
                const int row = wm * 32 + mt * 16 + gid;
                const uint2 lo = *reinterpret_cast<const uint2*>(
                    As + row * 24 + ks * 8 + 2 * tig);
                const uint2 hi = *reinterpret_cast<const uint2*>(
                    As + (row + 8) * 24 + ks * 8 + 2 * tig);
                aa[mt][0] = lo.x; aa[mt][1] = hi.x;
                aa[mt][2] = lo.y; aa[mt][3] = hi.y;
            }
#pragma unroll
            for (int nt = 0; nt < 4; ++nt) {
                const uint2 kb = *reinterpret_cast<const uint2*>(
                    Bs + (wn * 32 + nt * 8 + gid) * 24 + ks * 8 + 2 * tig);
                bb[nt][0] = kb.x; bb[nt][1] = kb.y;
            }
#pragma unroll
            for (int mt = 0; mt < 2; ++mt)
#pragma unroll
                for (int nt = 0; nt < 4; ++nt)
                    mma_f16(acc[mt][nt], aa[mt], bb[nt]);
        }
    }

#pragma unroll
    for (int mt = 0; mt < 2; ++mt) {
        const int r0 = m0 + wm * 32 + mt * 16 + gid;
#pragma unroll
        for (int nt = 0; nt < 4; ++nt) {
            const int cc = n0 + wn * 32 + nt * 8 + 2 * tig;
            *reinterpret_cast<float2*>(C + (size_t)r0 * N + cc) =
                make_float2(acc[mt][nt][0], acc[mt][nt][1]);
            *reinterpret_cast<float2*>(C + (size_t)(r0 + 8) * N + cc) =
                make_float2(acc[mt][nt][2], acc[mt][nt][3]);
        }
    }
}

__global__ void __launch_bounds__(256)
gemm_qkv_kernel(const float* __restrict__ x, const float* __restrict__ w) {
    gemm_nt_f16(x, w, g_qkv, N3_, D_);
}

__global__ void __launch_bounds__(256)
gemm_out_kernel(const float* __restrict__ w, float* __restrict__ out) {
    gemm_nt_f16(g_att, w, out, D_, D_);
}

// ---------------------------------------------------------------------------
// Flash attention (causal), f16 mma m16n8k16, R6 numerics (no online max,
// exp2 log2-domain, deferred l-reduction). 128 threads = 4 warps x 32 q-rows,
// BM=128, BN=64, occ 2. P fragments via cvt only (no shuffles). V fragments
// via ldmatrix.x4.trans.
// SMEM: Q[128][40 h2] + K[64][40 h2] + V[64][72 halfs] = 39936 B (static).
// ---------------------------------------------------------------------------
#define QST 40            // half2 stride for Q/K rows
#define VSTW 36           // V row stride in words (72 halfs = 144B)
#define QSCALE 0.180336879f   /* 0.125 * log2(e) */

__global__ void __launch_bounds__(128, 2) flash_f16_kernel() {
    __shared__ unsigned Qs[128 * QST];
    __shared__ unsigned Ks[64 * QST];
    __shared__ unsigned Vs[64 * VSTW];

    const int tid = threadIdx.x;
    const int w = tid >> 5;                // 0..3
    const int lane = tid & 31;
    const int gid = lane >> 2;
    const int tig = lane & 3;

    const int qt = (int)gridDim.y - 1 - (int)blockIdx.y;   // heavy tiles first
    const int q0 = qt * 128;
    const int bh = blockIdx.x;
    const int b = bh >> 3;
    const int h = bh & 7;

    const float* qptr = g_qkv + (size_t)b * T_ * N3_ + h * HD_;
    const float* kptr = qptr + D_;
    const float* vptr = qptr + 2 * D_;

    const int lr = tid >> 4;          // 0..7
    const int c = tid & 15;           // d-chunk of 4 floats
    const int pb = PBASE(c);

    // ---- stage Q (scaled into log2 domain, f16, interleaved) ----
#pragma unroll
    for (int i = 0; i < 16; ++i) {
        const int rr = lr + 8 * i;
        const float4 v = *reinterpret_cast<const float4*>(
            qptr + (size_t)(q0 + rr) * N3_ + c * 4);
        unsigned* p = Qs + rr * QST + pb;
        p[0] = cvt_h2(v.x * QSCALE, v.y * QSCALE);
        p[2] = cvt_h2(v.z * QSCALE, v.w * QSCALE);
    }

    // ---- preload first K/V tile ----
    float4 kreg[8], vreg[8];
#pragma unroll
    for (int i = 0; i < 8; ++i) {
        kreg[i] = *reinterpret_cast<const float4*>(kptr + (size_t)(lr + 8 * i) * N3_ + c * 4);
        vreg[i] = *reinterpret_cast<const float4*>(vptr + (size_t)(lr + 8 * i) * N3_ + c * 4);
    }

    float oc[2][8][4] = {};
    float li[2][2] = {};

    const int rowlo = q0 + w * 32;       // warp's lowest q row
    const int niter = 2 * (qt + 1);

    // ldmatrix per-lane base: row = 16ks + (lane&15), d-halfs = 16dtp + 8*((lane>>4)&1)
    const uint32_t vbase = smem_u32(Vs) + (uint32_t)(lane & 15) * 144u +
                           (uint32_t)((lane >> 4) & 1) * 16u;

    for (int it = 0; it < niter; ++it) {
        const int j0 = it * 64;
        __syncthreads();
        // store K interleaved (f16), V plain row-major (f16)
#pragma unroll
        for (int i = 0; i < 8; ++i) {
            const int rr = lr + 8 * i;
            unsigned* pk = Ks + rr * QST + pb;
            pk[0] = cvt_h2(kreg[i].x, kreg[i].y);
            pk[2] = cvt_h2(kreg[i].z, kreg[i].w);
            *reinterpret_cast<uint2*>(Vs + rr * VSTW + c * 2) =
                make_uint2(cvt_h2(vreg[i].x, vreg[i].y),
                           cvt_h2(vreg[i].z, vreg[i].w));
        }
        __syncthreads();

        if (it + 1 < niter) {
            const int jn = j0 + 64;
#pragma unroll
            for (int i = 0; i < 8; ++i) {
                kreg[i] = *reinterpret_cast<const float4*>(
                    kptr + (size_t)(jn + lr + 8 * i) * N3_ + c * 4);
                vreg[i] = *reinterpret_cast<const float4*>(
                    vptr + (size_t)(jn + lr + 8 * i) * N3_ + c * 4);
            }
        }

        if (j0 > rowlo + 31) continue;   // warp fully masked this iter

        // ---- S = Q K^T  (4 k-chunks of 16) ----
        float sc[2][8][4] = {};
#pragma unroll
        for (int ks = 0; ks < 4; ++ks) {
            unsigned qa[2][4];
#pragma unroll
            for (int mt = 0; mt < 2; ++mt) {
                const int row = w * 32 + mt * 16 + gid;
                const uint2 lo = *reinterpret_cast<const uint2*>(
                    Qs + row * QST + ks * 8 + 2 * tig);
                const uint2 hi = *reinterpret_cast<const uint2*>(
                    Qs + (row + 8) * QST + ks * 8 + 2 * tig);
                qa[mt][0] = lo.x; qa[mt][1] = hi.x;
                qa[mt][2] = lo.y; qa[mt][3] = hi.y;
            }
#pragma unroll
            for (int nt = 0; nt < 8; ++nt) {
                const uint2 kb = *reinterpret_cast<const uint2*>(
                    Ks + (nt * 8 + gid) * QST + ks * 8 + 2 * tig);
                unsigned bbr[2] = {kb.x, kb.y};
                mma_f16(sc[0][nt], qa[0], bbr);
                mma_f16(sc[1][nt], qa[1], bbr);
            }
        }

        // ---- causal mask ----
#pragma unroll
        for (int mt = 0; mt < 2; ++mt) {
            const int rbase = rowlo + mt * 16;
            if (j0 + 63 > rbase) {
                const int r0 = rbase + gid, r1 = rbase + gid + 8;
#pragma unroll
                for (int nt = 0; nt < 8; ++nt) {
                    const int cc = j0 + nt * 8 + 2 * tig;
                    if (cc > r0)     sc[mt][nt][0] = -1e30f;
                    if (cc + 1 > r0) sc[mt][nt][1] = -1e30f;
                    if (cc > r1)     sc[mt][nt][2] = -1e30f;
                    if (cc + 1 > r1) sc[mt][nt][3] = -1e30f;
                }
            }
        }

        // ---- exp2 + per-lane row sums ----
#pragma unroll
        for (int mt = 0; mt < 2; ++mt) {
            float s0 = 0.0f, s1 = 0.0f;
#pragma unroll
            for (int nt = 0; nt < 8; ++nt) {
                sc[mt][nt][0] = ex2(sc[mt][nt][0]);
                sc[mt][nt][1] = ex2(sc[mt][nt][1]);
                sc[mt][nt][2] = ex2(sc[mt][nt][2]);
                sc[mt][nt][3] = ex2(sc[mt][nt][3]);
                s0 += sc[mt][nt][0] + sc[mt][nt][1];
                s1 += sc[mt][nt][2] + sc[mt][nt][3];
            }
            li[mt][0] += s0;
            li[mt][1] += s1;
        }

        // ---- P fragments: pure cvt, NO shuffles (f16 A-layout = C-layout pairs)
        unsigned pa[2][4][4];
#pragma unroll
        for (int mt = 0; mt < 2; ++mt)
#pragma unroll
            for (int ks = 0; ks < 4; ++ks) {
                pa[mt][ks][0] = cvt_h2(sc[mt][2 * ks][0], sc[mt][2 * ks][1]);
                pa[mt][ks][1] = cvt_h2(sc[mt][2 * ks][2], sc[mt][2 * ks][3]);
                pa[mt][ks][2] = cvt_h2(sc[mt][2 * ks + 1][0], sc[mt][2 * ks + 1][1]);
                pa[mt][ks][3] = cvt_h2(sc[mt][2 * ks + 1][2], sc[mt][2 * ks + 1][3]);
            }

        // ---- O += P V  (V^T fragments via ldmatrix.x4.trans) ----
#pragma unroll
        for (int dtp = 0; dtp < 4; ++dtp) {
#pragma unroll
            for (int ks = 0; ks < 4; ++ks) {
                unsigned r0, r1, r2, r3;
                asm volatile(
                    "ldmatrix.sync.aligned.m8n8.x4.trans.shared.b16 "
                    "{%0,%1,%2,%3}, [%4];"
                    : "=r"(r0), "=r"(r1), "=r"(r2), "=r"(r3)
                    : "r"(vbase + (uint32_t)ks * 2304u + (uint32_t)dtp * 32u));
                unsigned vb0[2] = {r0, r1};
                unsigned vb1[2] = {r2, r3};
                mma_f16(oc[0][2 * dtp],     pa[0][ks], vb0);
                mma_f16(oc[1][2 * dtp],     pa[1][ks], vb0);
                mma_f16(oc[0][2 * dtp + 1], pa[0][ks], vb1);
                mma_f16(oc[1][2 * dtp + 1], pa[1][ks], vb1);
            }
        }
    }

    // ---- epilogue: quad-reduce row sums, normalize, store ----
#pragma unroll
    for (int mt = 0; mt < 2; ++mt) {
        float s0 = li[mt][0], s1 = li[mt][1];
        s0 += __shfl_xor_sync(0xffffffffu, s0, 1);
        s0 += __shfl_xor_sync(0xffffffffu, s0, 2);
        s1 += __shfl_xor_sync(0xffffffffu, s1, 1);
        s1 += __shfl_xor_sync(0xffffffffu, s1, 2);
        const float inv0 = 1.0f / s0;
        const float inv1 = 1.0f / s1;
        const int r0 = q0 + w * 32 + mt * 16 + gid;
        float* out0 = g_att + ((size_t)(b * T_ + r0)) * D_ + h * HD_;
        float* out1 = g_att + ((size_t)(b * T_ + r0 + 8)) * D_ + h * HD_;
#pragma unroll
        for (int dt = 0; dt < 8; ++dt) {
            const int cc = dt * 8 + 2 * tig;
            *reinterpret_cast<float2*>(out0 + cc) =
                make_float2(oc[mt][dt][0] * inv0, oc[mt][dt][1] * inv0);
            *reinterpret_cast<float2*>(out1 + cc) =
                make_float2(oc[mt][dt][2] * inv1, oc[mt][dt][3] * inv1);
        }
    }
}

// ---------------------------------------------------------------------------
extern "C" void kernel_launch(void* const* d_in, const int* in_sizes, int n_in,
                              void* d_out, int out_size) {
    const float* x = nullptr;
    const float* w_qkv = nullptr;
    const float* w_out = nullptr;
    for (int i = 0; i < n_in; ++i) {
        if (in_sizes[i] == M_ * D_)       x = (const float*)d_in[i];
        else if (in_sizes[i] == N3_ * D_) w_qkv = (const float*)d_in[i];
        else if (in_sizes[i] == D_ * D_)  w_out = (const float*)d_in[i];
    }
    float* out = (float*)d_out;

    gemm_qkv_kernel<<<dim3(N3_ / 64, M_ / 128), 256>>>(x, w_qkv);
    // 512 blocks (16 bh x 32 q-tiles), 128 threads, 2 CTAs/SM
    flash_f16_kernel<<<dim3(B_ * H_, T_ / 128), 128>>>();
    gemm_out_kernel<<<dim3(D_ / 64, M_ / 128), 256>>>(w_out, out);
}

// round 12
// speedup vs baseline: 1.9959x; 1.2022x over previous
#include <cuda_runtime.h>
#include <cuda_fp16.h>
#include <cstdint>

#define B_   2
#define T_   4096
#define D_   512
#define H_   8
#define HD_  64
#define M_   (B_ * T_)
#define N3_  (3 * D_)

__device__ float g_qkv[M_ * N3_];
__device__ float g_att[M_ * D_];

// ---------------------------------------------------------------------------
// helpers
// ---------------------------------------------------------------------------
__device__ __forceinline__ unsigned cvt_h2(float lo, float hi) {
    unsigned r;
    asm("cvt.rn.f16x2.f32 %0, %1, %2;" : "=r"(r) : "f"(hi), "f"(lo));
    return r;
}
__device__ __forceinline__ float ex2(float x) {
    float r;
    asm("ex2.approx.ftz.f32 %0, %1;" : "=f"(r) : "f"(x));
    return r;
}
__device__ __forceinline__ void mma_f16(float d[4], const unsigned a[4],
                                        const unsigned b[2]) {
    asm volatile(
        "mma.sync.aligned.m16n8k16.row.col.f32.f16.f16.f32 "
        "{%0,%1,%2,%3}, {%4,%5,%6,%7}, {%8,%9}, {%0,%1,%2,%3};\n"
        : "+f"(d[0]), "+f"(d[1]), "+f"(d[2]), "+f"(d[3])
        : "r"(a[0]), "r"(a[1]), "r"(a[2]), "r"(a[3]), "r"(b[0]), "r"(b[1]));
}
__device__ __forceinline__ uint32_t smem_u32(const void* p) {
    uint32_t a;
    asm("{ .reg .u64 t; cvta.to.shared.u64 t, %1; cvt.u32.u64 %0, t; }"
        : "=r"(a) : "l"(p));
    return a;
}

// 16-halfs chunk interleave: within chunk ks, half2 slot ks*8+2t   = (d 16ks+2t, +1)
//                                            half2 slot ks*8+2t+1 = (d 16ks+2t+8, +9)
// staging: float4 at d=4c -> slots pb, pb+2 with pb = (c>>2)*8 + 4*(c&1) + ((c&3)>>1)
#define PBASE(c) (((c) >> 2) * 8 + 4 * ((c) & 1) + (((c) & 3) >> 1))

// ---------------------------------------------------------------------------
// NT GEMM, f16 mma m16n8k16: C[m,n] = sum_k A[m,k]*B[n,k]
// BM=128, BN=128, BK=32, 8 warps (4x2), warp tile 32x64.
// 32 mmas per mainloop iter (issue-density fix for the f16 k16 path).
// SMEM rows: 16 half2 data, stride 24 half2 -> conflict-free LDS.64 fragments.
// ---------------------------------------------------------------------------
__device__ __forceinline__ void gemm_nt_f16(const float* __restrict__ A,
                                            const float* __restrict__ Bm,
                                            float* __restrict__ C,
                                            int N, int K) {
    __shared__ unsigned As[128 * 24];
    __shared__ unsigned Bs[128 * 24];

    const int tid = threadIdx.x;
    const int w = tid >> 5;
    const int lane = tid & 31;
    const int gid = lane >> 2;
    const int tig = lane & 3;
    const int wm = w >> 1;            // 0..3 -> 32 rows
    const int wn = w & 1;             // 0..1 -> 64 cols

    const int m0 = blockIdx.y * 128;
    const int n0 = blockIdx.x * 128;

    const int lr = tid >> 3;          // 0..31
    const int c = tid & 7;            // k-chunk of 4 floats
    const int pb = PBASE(c);

    float acc[2][8][4] = {};

    for (int k0 = 0; k0 < K; k0 += 32) {
        float4 a4[4], b4[4];
#pragma unroll
        for (int i = 0; i < 4; ++i) {
            a4[i] = *reinterpret_cast<const float4*>(
                A + (size_t)(m0 + lr + 32 * i) * K + k0 + c * 4);
            b4[i] = *reinterpret_cast<const float4*>(
                Bm + (size_t)(n0 + lr + 32 * i) * K + k0 + c * 4);
        }
        __syncthreads();
#pragma unroll
        for (int i = 0; i < 4; ++i) {
            unsigned* p = As + (lr + 32 * i) * 24 + pb;
            p[0] = cvt_h2(a4[i].x, a4[i].y);
            p[2] = cvt_h2(a4[i].z, a4[i].w);
            unsigned* q = Bs + (lr + 32 * i) * 24 + pb;
            q[0] = cvt_h2(b4[i].x, b4[i].y);
            q[2] = cvt_h2(b4[i].z, b4[i].w);
        }
        __syncthreads();

#pragma unroll
        for (int ks = 0; ks < 2; ++ks) {
            unsigned aa[2][4], bb[8][2];
#pragma unroll
            for (int mt = 0; mt < 2; ++mt) {
                const int row = wm * 32 + mt * 16 + gid;
                const uint2 lo = *reinterpret_cast<const uint2*>(
                    As + row * 24 + ks * 8 + 2 * tig);
                const uint2 hi = *reinterpret_cast<const uint2*>(
                    As + (row + 8) * 24 + ks * 8 + 2 * tig);
                aa[mt][0] = lo.x; aa[mt][1] = hi.x;
                aa[mt][2] = lo.y; aa[mt][3] = hi.y;
            }
#pragma unroll
            for (int nt = 0; nt < 8; ++nt) {
                const uint2 kb = *reinterpret_cast<const uint2*>(
                    Bs + (wn * 64 + nt * 8 + gid) * 24 + ks * 8 + 2 * tig);
                bb[nt][0] = kb.x; bb[nt][1] = kb.y;
            }
#pragma unroll
            for (int mt = 0; mt < 2; ++mt)
#pragma unroll
                for (int nt = 0; nt < 8; ++nt)
                    mma_f16(acc[mt][nt], aa[mt], bb[nt]);
        }
    }

#pragma unroll
    for (int mt = 0; mt < 2; ++mt) {
        const int r0 = m0 + wm * 32 + mt * 16 + gid;
#pragma unroll
        for (int nt = 0; nt < 8; ++nt) {
            const int cc = n0 + wn * 64 + nt * 8 + 2 * tig;
            *reinterpret_cast<float2*>(C + (size_t)r0 * N + cc) =
                make_float2(acc[mt][nt][0], acc[mt][nt][1]);
            *reinterpret_cast<float2*>(C + (size_t)(r0 + 8) * N + cc) =
                make_float2(acc[mt][nt][2], acc[mt][nt][3]);
        }
    }
}

__global__ void __launch_bounds__(256)
gemm_qkv_kernel(const float* __restrict__ x, const float* __restrict__ w) {
    gemm_nt_f16(x, w, g_qkv, N3_, D_);
}

__global__ void __launch_bounds__(256)
gemm_out_kernel(const float* __restrict__ w, float* __restrict__ out) {
    gemm_nt_f16(g_att, w, out, D_, D_);
}

// ---------------------------------------------------------------------------
// Flash attention (causal), f16 mma m16n8k16 — UNCHANGED from R11 (at ~93%
// of the f16 roofline). 128 threads = 4 warps x 32 q-rows, BM=128, BN=64.
// ---------------------------------------------------------------------------
#define QST 40            // half2 stride for Q/K rows
#define VSTW 36           // V row stride in words (72 halfs = 144B)
#define QSCALE 0.180336879f   /* 0.125 * log2(e) */

__global__ void __launch_bounds__(128, 2) flash_f16_kernel() {
    __shared__ unsigned Qs[128 * QST];
    __shared__ unsigned Ks[64 * QST];
    __shared__ unsigned Vs[64 * VSTW];

    const int tid = threadIdx.x;
    const int w = tid >> 5;                // 0..3
    const int lane = tid & 31;
    const int gid = lane >> 2;
    const int tig = lane & 3;

    const int qt = (int)gridDim.y - 1 - (int)blockIdx.y;   // heavy tiles first
    const int q0 = qt * 128;
    const int bh = blockIdx.x;
    const int b = bh >> 3;
    const int h = bh & 7;

    const float* qptr = g_qkv + (size_t)b * T_ * N3_ + h * HD_;
    const float* kptr = qptr + D_;
    const float* vptr = qptr + 2 * D_;

    const int lr = tid >> 4;          // 0..7
    const int c = tid & 15;           // d-chunk of 4 floats
    const int pb = PBASE(c);

    // ---- stage Q (scaled into log2 domain, f16, interleaved) ----
#pragma unroll
    for (int i = 0; i < 16; ++i) {
        const int rr = lr + 8 * i;
        const float4 v = *reinterpret_cast<const float4*>(
            qptr + (size_t)(q0 + rr) * N3_ + c * 4);
        unsigned* p = Qs + rr * QST + pb;
        p[0] = cvt_h2(v.x * QSCALE, v.y * QSCALE);
        p[2] = cvt_h2(v.z * QSCALE, v.w * QSCALE);
    }

    // ---- preload first K/V tile ----
    float4 kreg[8], vreg[8];
#pragma unroll
    for (int i = 0; i < 8; ++i) {
        kreg[i] = *reinterpret_cast<const float4*>(kptr + (size_t)(lr + 8 * i) * N3_ + c * 4);
        vreg[i] = *reinterpret_cast<const float4*>(vptr + (size_t)(lr + 8 * i) * N3_ + c * 4);
    }

    float oc[2][8][4] = {};
    float li[2][2] = {};

    const int rowlo = q0 + w * 32;       // warp's lowest q row
    const int niter = 2 * (qt + 1);

    // ldmatrix per-lane base: row = 16ks + (lane&15), d-halfs = 16dtp + 8*((lane>>4)&1)
    const uint32_t vbase = smem_u32(Vs) + (uint32_t)(lane & 15) * 144u +
                           (uint32_t)((lane >> 4) & 1) * 16u;

    for (int it = 0; it < niter; ++it) {
        const int j0 = it * 64;
        __syncthreads();
        // store K interleaved (f16), V plain row-major (f16)
#pragma unroll
        for (int i = 0; i < 8; ++i) {
            const int rr = lr + 8 * i;
            unsigned* pk = Ks + rr * QST + pb;
            pk[0] = cvt_h2(kreg[i].x, kreg[i].y);
            pk[2] = cvt_h2(kreg[i].z, kreg[i].w);
            *reinterpret_cast<uint2*>(Vs + rr * VSTW + c * 2) =
                make_uint2(cvt_h2(vreg[i].x, vreg[i].y),
                           cvt_h2(vreg[i].z, vreg[i].w));
        }
        __syncthreads();

        if (it + 1 < niter) {
            const int jn = j0 + 64;
#pragma unroll
            for (int i = 0; i < 8; ++i) {
                kreg[i] = *reinterpret_cast<const float4*>(
                    kptr + (size_t)(jn + lr + 8 * i) * N3_ + c * 4);
                vreg[i] = *reinterpret_cast<const float4*>(
                    vptr + (size_t)(jn + lr + 8 * i) * N3_ + c * 4);
            }
        }

        if (j0 > rowlo + 31) continue;   // warp fully masked this iter

        // ---- S = Q K^T  (4 k-chunks of 16) ----
        float sc[2][8][4] = {};
#pragma unroll
        for (int ks = 0; ks < 4; ++ks) {
            unsigned qa[2][4];
#pragma unroll
            for (int mt = 0; mt < 2; ++mt) {
                const int row = w * 32 + mt * 16 + gid;
                const uint2 lo = *reinterpret_cast<const uint2*>(
                    Qs + row * QST + ks * 8 + 2 * tig);
                const uint2 hi = *reinterpret_cast<const uint2*>(
                    Qs + (row + 8) * QST + ks * 8 + 2 * tig);
                qa[mt][0] = lo.x; qa[mt][1] = hi.x;
                qa[mt][2] = lo.y; qa[mt][3] = hi.y;
            }
#pragma unroll
            for (int nt = 0; nt < 8; ++nt) {
                const uint2 kb = *reinterpret_cast<const uint2*>(
                    Ks + (nt * 8 + gid) * QST + ks * 8 + 2 * tig);
                unsigned bbr[2] = {kb.x, kb.y};
                mma_f16(sc[0][nt], qa[0], bbr);
                mma_f16(sc[1][nt], qa[1], bbr);
            }
        }

        // ---- causal mask ----
#pragma unroll
        for (int mt = 0; mt < 2; ++mt) {
            const int rbase = rowlo + mt * 16;
            if (j0 + 63 > rbase) {
                const int r0 = rbase + gid, r1 = rbase + gid + 8;
#pragma unroll
                for (int nt = 0; nt < 8; ++nt) {
                    const int cc = j0 + nt * 8 + 2 * tig;
                    if (cc > r0)     sc[mt][nt][0] = -1e30f;
                    if (cc + 1 > r0) sc[mt][nt][1] = -1e30f;
                    if (cc > r1)     sc[mt][nt][2] = -1e30f;
                    if (cc + 1 > r1) sc[mt][nt][3] = -1e30f;
                }
            }
        }

        // ---- exp2 + per-lane row sums ----
#pragma unroll
        for (int mt = 0; mt < 2; ++mt) {
            float s0 = 0.0f, s1 = 0.0f;
#pragma unroll
            for (int nt = 0; nt < 8; ++nt) {
                sc[mt][nt][0] = ex2(sc[mt][nt][0]);
                sc[mt][nt][1] = ex2(sc[mt][nt][1]);
                sc[mt][nt][2] = ex2(sc[mt][nt][2]);
                sc[mt][nt][3] = ex2(sc[mt][nt][3]);
                s0 += sc[mt][nt][0] + sc[mt][nt][1];
                s1 += sc[mt][nt][2] + sc[mt][nt][3];
            }
            li[mt][0] += s0;
            li[mt][1] += s1;
        }

        // ---- P fragments: pure cvt, NO shuffles ----
        unsigned pa[2][4][4];
#pragma unroll
        for (int mt = 0; mt < 2; ++mt)
#pragma unroll
            for (int ks = 0; ks < 4; ++ks) {
                pa[mt][ks][0] = cvt_h2(sc[mt][2 * ks][0], sc[mt][2 * ks][1]);
                pa[mt][ks][1] = cvt_h2(sc[mt][2 * ks][2], sc[mt][2 * ks][3]);
                pa[mt][ks][2] = cvt_h2(sc[mt][2 * ks + 1][0], sc[mt][2 * ks + 1][1]);
                pa[mt][ks][3] = cvt_h2(sc[mt][2 * ks + 1][2], sc[mt][2 * ks + 1][3]);
            }

        // ---- O += P V  (V^T fragments via ldmatrix.x4.trans) ----
#pragma unroll
        for (int dtp = 0; dtp < 4; ++dtp) {
#pragma unroll
            for (int ks = 0; ks < 4; ++ks) {
                unsigned r0, r1, r2, r3;
                asm volatile(
                    "ldmatrix.sync.aligned.m8n8.x4.trans.shared.b16 "
                    "{%0,%1,%2,%3}, [%4];"
                    : "=r"(r0), "=r"(r1), "=r"(r2), "=r"(r3)
                    : "r"(vbase + (uint32_t)ks * 2304u + (uint32_t)dtp * 32u));
                unsigned vb0[2] = {r0, r1};
                unsigned vb1[2] = {r2, r3};
                mma_f16(oc[0][2 * dtp],     pa[0][ks], vb0);
                mma_f16(oc[1][2 * dtp],     pa[1][ks], vb0);
                mma_f16(oc[0][2 * dtp + 1], pa[0][ks], vb1);
                mma_f16(oc[1][2 * dtp + 1], pa[1][ks], vb1);
            }
        }
    }

    // ---- epilogue: quad-reduce row sums, normalize, store ----
#pragma unroll
    for (int mt = 0; mt < 2; ++mt) {
        float s0 = li[mt][0], s1 = li[mt][1];
        s0 += __shfl_xor_sync(0xffffffffu, s0, 1);
        s0 += __shfl_xor_sync(0xffffffffu, s0, 2);
        s1 += __shfl_xor_sync(0xffffffffu, s1, 1);
        s1 += __shfl_xor_sync(0xffffffffu, s1, 2);
        const float inv0 = 1.0f / s0;
        const float inv1 = 1.0f / s1;
        const int r0 = q0 + w * 32 + mt * 16 + gid;
        float* out0 = g_att + ((size_t)(b * T_ + r0)) * D_ + h * HD_;
        float* out1 = g_att + ((size_t)(b * T_ + r0 + 8)) * D_ + h * HD_;
#pragma unroll
        for (int dt = 0; dt < 8; ++dt) {
            const int cc = dt * 8 + 2 * tig;
            *reinterpret_cast<float2*>(out0 + cc) =
                make_float2(oc[mt][dt][0] * inv0, oc[mt][dt][1] * inv0);
            *reinterpret_cast<float2*>(out1 + cc) =
                make_float2(oc[mt][dt][2] * inv1, oc[mt][dt][3] * inv1);
        }
    }
}

// ---------------------------------------------------------------------------
extern "C" void kernel_launch(void* const* d_in, const int* in_sizes, int n_in,
                              void* d_out, int out_size) {
    const float* x = nullptr;
    const float* w_qkv = nullptr;
    const float* w_out = nullptr;
    for (int i = 0; i < n_in; ++i) {
        if (in_sizes[i] == M_ * D_)       x = (const float*)d_in[i];
        else if (in_sizes[i] == N3_ * D_) w_qkv = (const float*)d_in[i];
        else if (in_sizes[i] == D_ * D_)  w_out = (const float*)d_in[i];
    }
    float* out = (float*)d_out;

    gemm_qkv_kernel<<<dim3(N3_ / 128, M_ / 128), 256>>>(x, w_qkv);
    // 512 blocks (16 bh x 32 q-tiles), 128 threads, 2 CTAs/SM
    flash_f16_kernel<<<dim3(B_ * H_, T_ / 128), 128>>>();
    gemm_out_kernel<<<dim3(D_ / 128, M_ / 128), 256>>>(w_out, out);
}

// round 13
// speedup vs baseline: 2.0252x; 1.0147x over previous
#include <cuda_runtime.h>
#include <cuda_fp16.h>
#include <cstdint>

#define B_   2
#define T_   4096
#define D_   512
#define H_   8
#define HD_  64
#define M_   (B_ * T_)
#define N3_  (3 * D_)

__device__ float g_qkv[M_ * N3_];
__device__ float g_att[M_ * D_];

// ---------------------------------------------------------------------------
// helpers
// ---------------------------------------------------------------------------
__device__ __forceinline__ unsigned cvt_h2(float lo, float hi) {
    unsigned r;
    asm("cvt.rn.f16x2.f32 %0, %1, %2;" : "=r"(r) : "f"(hi), "f"(lo));
    return r;
}
__device__ __forceinline__ float ex2(float x) {
    float r;
    asm("ex2.approx.ftz.f32 %0, %1;" : "=f"(r) : "f"(x));
    return r;
}
__device__ __forceinline__ void mma_f16(float d[4], const unsigned a[4],
                                        const unsigned b[2]) {
    asm volatile(
        "mma.sync.aligned.m16n8k16.row.col.f32.f16.f16.f32 "
        "{%0,%1,%2,%3}, {%4,%5,%6,%7}, {%8,%9}, {%0,%1,%2,%3};\n"
        : "+f"(d[0]), "+f"(d[1]), "+f"(d[2]), "+f"(d[3])
        : "r"(a[0]), "r"(a[1]), "r"(a[2]), "r"(a[3]), "r"(b[0]), "r"(b[1]));
}
__device__ __forceinline__ uint32_t smem_u32(const void* p) {
    uint32_t a;
    asm("{ .reg .u64 t; cvta.to.shared.u64 t, %1; cvt.u32.u64 %0, t; }"
        : "=r"(a) : "l"(p));
    return a;
}
__device__ __forceinline__ void cp16(uint32_t dst, const void* src) {
    asm volatile("cp.async.cg.shared.global [%0], [%1], 16;"
                 :: "r"(dst), "l"(src) : "memory");
}
#define CP_COMMIT() asm volatile("cp.async.commit_group;" ::: "memory")
#define CP_WAIT1()  asm volatile("cp.async.wait_group 1;" ::: "memory")
#define CP_WAIT0()  asm volatile("cp.async.wait_group 0;" ::: "memory")

// 16-halfs chunk interleave (flash): float4 at d=4c -> slots pb, pb+2
#define PBASE(c) (((c) >> 2) * 8 + 4 * ((c) & 1) + (((c) & 3) >> 1))

// ---------------------------------------------------------------------------
// NT GEMM, f16 mma m16n8k16, cp.async 2-stage pipeline, fp32 smem.
// BM=128, BN=128, BK=32, 8 warps (4x2), warp tile 32x64, 32 mmas/iter.
// smem row stride 40 floats: conflict-free LDS.64 fragments; 16B-aligned rows.
// ---------------------------------------------------------------------------
#define GST   40                    // smem row stride (floats)
#define GA_F  (128 * GST)           // floats per A (or B) tile buffer
#define GBUF_F (2 * GA_F)           // floats per stage (A+B)
#define GEMM_SMEM (2 * GBUF_F * 4)  // 81920 B

__device__ __forceinline__ void gemm_cp_tile(uint32_t sbase, int s,
                                             const float* __restrict__ A,
                                             const float* __restrict__ Bm,
                                             int m0, int n0, int K, int k0,
                                             int lr, int c) {
    const uint32_t da = sbase + (uint32_t)(s * GBUF_F + lr * GST + c * 4) * 4u;
    const uint32_t db = da + (uint32_t)GA_F * 4u;
#pragma unroll
    for (int i = 0; i < 4; ++i) {
        cp16(da + (uint32_t)(i * 32 * GST) * 4u,
             A + (size_t)(m0 + lr + 32 * i) * K + k0 + c * 4);
        cp16(db + (uint32_t)(i * 32 * GST) * 4u,
             Bm + (size_t)(n0 + lr + 32 * i) * K + k0 + c * 4);
    }
    CP_COMMIT();
}

__device__ __forceinline__ void gemm_nt_f16ca(const float* __restrict__ A,
                                              const float* __restrict__ Bm,
                                              float* __restrict__ C,
                                              int N, int K) {
    extern __shared__ float gs[];
    const uint32_t sbase = smem_u32(gs);

    const int tid = threadIdx.x;
    const int w = tid >> 5;
    const int lane = tid & 31;
    const int gid = lane >> 2;
    const int tig = lane & 3;
    const int wm = w >> 1;            // 0..3 -> 32 rows
    const int wn = w & 1;             // 0..1 -> 64 cols

    const int m0 = blockIdx.y * 128;
    const int n0 = blockIdx.x * 128;

    const int lr = tid >> 3;          // 0..31
    const int c = tid & 7;            // 16B chunk in 128B k-row

    const int niter = K / 32;         // 16

    // prologue: stage tiles 0 and 1
    gemm_cp_tile(sbase, 0, A, Bm, m0, n0, K, 0, lr, c);
    gemm_cp_tile(sbase, 1, A, Bm, m0, n0, K, 32, lr, c);

    float acc[2][8][4] = {};

#pragma unroll 1
    for (int it = 0; it < niter; ++it) {
        const int s = it & 1;
        if (it + 1 < niter) { CP_WAIT1(); } else { CP_WAIT0(); }
        __syncthreads();              // buf[s] fully valid for all warps

        const float* As = gs + s * GBUF_F;
        const float* Bs = As + GA_F;

#pragma unroll
        for (int ks = 0; ks < 2; ++ks) {
            unsigned aa[2][4], bb[8][2];
#pragma unroll
            for (int mt = 0; mt < 2; ++mt) {
                const int row = wm * 32 + mt * 16 + gid;
                const float* p = As + row * GST + ks * 16 + 2 * tig;
                const float2 v00 = *reinterpret_cast<const float2*>(p);
                const float2 v01 = *reinterpret_cast<const float2*>(p + 8);
                const float2 v10 = *reinterpret_cast<const float2*>(p + 8 * GST);
                const float2 v11 = *reinterpret_cast<const float2*>(p + 8 * GST + 8);
                aa[mt][0] = cvt_h2(v00.x, v00.y);
                aa[mt][1] = cvt_h2(v10.x, v10.y);
                aa[mt][2] = cvt_h2(v01.x, v01.y);
                aa[mt][3] = cvt_h2(v11.x, v11.y);
            }
#pragma unroll
            for (int nt = 0; nt < 8; ++nt) {
                const float* p = Bs + (wn * 64 + nt * 8 + gid) * GST + ks * 16 + 2 * tig;
                const float2 u0 = *reinterpret_cast<const float2*>(p);
                const float2 u1 = *reinterpret_cast<const float2*>(p + 8);
                bb[nt][0] = cvt_h2(u0.x, u0.y);
                bb[nt][1] = cvt_h2(u1.x, u1.y);
            }
#pragma unroll
            for (int mt = 0; mt < 2; ++mt)
#pragma unroll
                for (int nt = 0; nt < 8; ++nt)
                    mma_f16(acc[mt][nt], aa[mt], bb[nt]);
        }

        __syncthreads();              // all warps done reading buf[s]
        if (it + 2 < niter)
            gemm_cp_tile(sbase, s, A, Bm, m0, n0, K, (it + 2) * 32, lr, c);
    }

#pragma unroll
    for (int mt = 0; mt < 2; ++mt) {
        const int r0 = m0 + wm * 32 + mt * 16 + gid;
#pragma unroll
        for (int nt = 0; nt < 8; ++nt) {
            const int cc = n0 + wn * 64 + nt * 8 + 2 * tig;
            *reinterpret_cast<float2*>(C + (size_t)r0 * N + cc) =
                make_float2(acc[mt][nt][0], acc[mt][nt][1]);
            *reinterpret_cast<float2*>(C + (size_t)(r0 + 8) * N + cc) =
                make_float2(acc[mt][nt][2], acc[mt][nt][3]);
        }
    }
}

__global__ void __launch_bounds__(256)
gemm_qkv_kernel(const float* __restrict__ x, const float* __restrict__ w) {
    gemm_nt_f16ca(x, w, g_qkv, N3_, D_);
}

__global__ void __launch_bounds__(256)
gemm_out_kernel(const float* __restrict__ w, float* __restrict__ out) {
    gemm_nt_f16ca(g_att, w, out, D_, D_);
}

// ---------------------------------------------------------------------------
// Flash attention (causal), f16 mma m16n8k16 — UNCHANGED from R11/R12
// (at ~93% of the f16 roofline). 128 threads = 4 warps x 32 q-rows.
// ---------------------------------------------------------------------------
#define QST 40            // half2 stride for Q/K rows
#define VSTW 36           // V row stride in words (72 halfs = 144B)
#define QSCALE 0.180336879f   /* 0.125 * log2(e) */

__global__ void __launch_bounds__(128, 2) flash_f16_kernel() {
    __shared__ unsigned Qs[128 * QST];
    __shared__ unsigned Ks[64 * QST];
    __shared__ unsigned Vs[64 * VSTW];

    const int tid = threadIdx.x;
    const int w = tid >> 5;                // 0..3
    const int lane = tid & 31;
    const int gid = lane >> 2;
    const int tig = lane & 3;

    const int qt = (int)gridDim.y - 1 - (int)blockIdx.y;   // heavy tiles first
    const int q0 = qt * 128;
    const int bh = blockIdx.x;
    const int b = bh >> 3;
    const int h = bh & 7;

    const float* qptr = g_qkv + (size_t)b * T_ * N3_ + h * HD_;
    const float* kptr = qptr + D_;
    const float* vptr = qptr + 2 * D_;

    const int lr = tid >> 4;          // 0..7
    const int c = tid & 15;           // d-chunk of 4 floats
    const int pb = PBASE(c);

    // ---- stage Q (scaled into log2 domain, f16, interleaved) ----
#pragma unroll
    for (int i = 0; i < 16; ++i) {
        const int rr = lr + 8 * i;
        const float4 v = *reinterpret_cast<const float4*>(
            qptr + (size_t)(q0 + rr) * N3_ + c * 4);
        unsigned* p = Qs + rr * QST + pb;
        p[0] = cvt_h2(v.x * QSCALE, v.y * QSCALE);
        p[2] = cvt_h2(v.z * QSCALE, v.w * QSCALE);
    }

    // ---- preload first K/V tile ----
    float4 kreg[8], vreg[8];
#pragma unroll
    for (int i = 0; i < 8; ++i) {
        kreg[i] = *reinterpret_cast<const float4*>(kptr + (size_t)(lr + 8 * i) * N3_ + c * 4);
        vreg[i] = *reinterpret_cast<const float4*>(vptr + (size_t)(lr + 8 * i) * N3_ + c * 4);
    }

    float oc[2][8][4] = {};
    float li[2][2] = {};

    const int rowlo = q0 + w * 32;       // warp's lowest q row
    const int niter = 2 * (qt + 1);

    // ldmatrix per-lane base: row = 16ks + (lane&15), d-halfs = 16dtp + 8*((lane>>4)&1)
    const uint32_t vbase = smem_u32(Vs) + (uint32_t)(lane & 15) * 144u +
                           (uint32_t)((lane >> 4) & 1) * 16u;

    for (int it = 0; it < niter; ++it) {
        const int j0 = it * 64;
        __syncthreads();
        // store K interleaved (f16), V plain row-major (f16)
#pragma unroll
        for (int i = 0; i < 8; ++i) {
            const int rr = lr + 8 * i;
            unsigned* pk = Ks + rr * QST + pb;
            pk[0] = cvt_h2(kreg[i].x, kreg[i].y);
            pk[2] = cvt_h2(kreg[i].z, kreg[i].w);
            *reinterpret_cast<uint2*>(Vs + rr * VSTW + c * 2) =
                make_uint2(cvt_h2(vreg[i].x, vreg[i].y),
                           cvt_h2(vreg[i].z, vreg[i].w));
        }
        __syncthreads();

        if (it + 1 < niter) {
            const int jn = j0 + 64;
#pragma unroll
            for (int i = 0; i < 8; ++i) {
                kreg[i] = *reinterpret_cast<const float4*>(
                    kptr + (size_t)(jn + lr + 8 * i) * N3_ + c * 4);
                vreg[i] = *reinterpret_cast<const float4*>(
                    vptr + (size_t)(jn + lr + 8 * i) * N3_ + c * 4);
            }
        }

        if (j0 > rowlo + 31) continue;   // warp fully masked this iter

        // ---- S = Q K^T  (4 k-chunks of 16) ----
        float sc[2][8][4] = {};
#pragma unroll
        for (int ks = 0; ks < 4; ++ks) {
            unsigned qa[2][4];
#pragma unroll
            for (int mt = 0; mt < 2; ++mt) {
                const int row = w * 32 + mt * 16 + gid;
                const uint2 lo = *reinterpret_cast<const uint2*>(
                    Qs + row * QST + ks * 8 + 2 * tig);
                const uint2 hi = *reinterpret_cast<const uint2*>(
                    Qs + (row + 8) * QST + ks * 8 + 2 * tig);
                qa[mt][0] = lo.x; qa[mt][1] = hi.x;
                qa[mt][2] = lo.y; qa[mt][3] = hi.y;
            }
#pragma unroll
            for (int nt = 0; nt < 8; ++nt) {
                const uint2 kb = *reinterpret_cast<const uint2*>(
                    Ks + (nt * 8 + gid) * QST + ks * 8 + 2 * tig);
                unsigned bbr[2] = {kb.x, kb.y};
                mma_f16(sc[0][nt], qa[0], bbr);
                mma_f16(sc[1][nt], qa[1], bbr);
            }
        }

        // ---- causal mask ----
#pragma unroll
        for (int mt = 0; mt < 2; ++mt) {
            const int rbase = rowlo + mt * 16;
            if (j0 + 63 > rbase) {
                const int r0 = rbase + gid, r1 = rbase + gid + 8;
#pragma unroll
                for (int nt = 0; nt < 8; ++nt) {
                    const int cc = j0 + nt * 8 + 2 * tig;
                    if (cc > r0)     sc[mt][nt][0] = -1e30f;
                    if (cc + 1 > r0) sc[mt][nt][1] = -1e30f;
                    if (cc > r1)     sc[mt][nt][2] = -1e30f;
                    if (cc + 1 > r1) sc[mt][nt][3] = -1e30f;
                }
            }
        }

        // ---- exp2 + per-lane row sums ----
#pragma unroll
        for (int mt = 0; mt < 2; ++mt) {
            float s0 = 0.0f, s1 = 0.0f;
#pragma unroll
            for (int nt = 0; nt < 8; ++nt) {
                sc[mt][nt][0] = ex2(sc[mt][nt][0]);
                sc[mt][nt][1] = ex2(sc[mt][nt][1]);
                sc[mt][nt][2] = ex2(sc[mt][nt][2]);
                sc[mt][nt][3] = ex2(sc[mt][nt][3]);
                s0 += sc[mt][nt][0] + sc[mt][nt][1];
                s1 += sc[mt][nt][2] + sc[mt][nt][3];
            }
            li[mt][0] += s0;
            li[mt][1] += s1;
        }

        // ---- P fragments: pure cvt, NO shuffles ----
        unsigned pa[2][4][4];
#pragma unroll
        for (int mt = 0; mt < 2; ++mt)
#pragma unroll
            for (int ks = 0; ks < 4; ++ks) {
                pa[mt][ks][0] = cvt_h2(sc[mt][2 * ks][0], sc[mt][2 * ks][1]);
                pa[mt][ks][1] = cvt_h2(sc[mt][2 * ks][2], sc[mt][2 * ks][3]);
                pa[mt][ks][2] = cvt_h2(sc[mt][2 * ks + 1][0], sc[mt][2 * ks + 1][1]);
                pa[mt][ks][3] = cvt_h2(sc[mt][2 * ks + 1][2], sc[mt][2 * ks + 1][3]);
            }

        // ---- O += P V  (V^T fragments via ldmatrix.x4.trans) ----
#pragma unroll
        for (int dtp = 0; dtp < 4; ++dtp) {
#pragma unroll
            for (int ks = 0; ks < 4; ++ks) {
                unsigned r0, r1, r2, r3;
                asm volatile(
                    "ldmatrix.sync.aligned.m8n8.x4.trans.shared.b16 "
                    "{%0,%1,%2,%3}, [%4];"
                    : "=r"(r0), "=r"(r1), "=r"(r2), "=r"(r3)
                    : "r"(vbase + (uint32_t)ks * 2304u + (uint32_t)dtp * 32u));
                unsigned vb0[2] = {r0, r1};
                unsigned vb1[2] = {r2, r3};
                mma_f16(oc[0][2 * dtp],     pa[0][ks], vb0);
                mma_f16(oc[1][2 * dtp],     pa[1][ks], vb0);
                mma_f16(oc[0][2 * dtp + 1], pa[0][ks], vb1);
                mma_f16(oc[1][2 * dtp + 1], pa[1][ks], vb1);
            }
        }
    }

    // ---- epilogue: quad-reduce row sums, normalize, store ----
#pragma unroll
    for (int mt = 0; mt < 2; ++mt) {
        float s0 = li[mt][0], s1 = li[mt][1];
        s0 += __shfl_xor_sync(0xffffffffu, s0, 1);
        s0 += __shfl_xor_sync(0xffffffffu, s0, 2);
        s1 += __shfl_xor_sync(0xffffffffu, s1, 1);
        s1 += __shfl_xor_sync(0xffffffffu, s1, 2);
        const float inv0 = 1.0f / s0;
        const float inv1 = 1.0f / s1;
        const int r0 = q0 + w * 32 + mt * 16 + gid;
        float* out0 = g_att + ((size_t)(b * T_ + r0)) * D_ + h * HD_;
        float* out1 = g_att + ((size_t)(b * T_ + r0 + 8)) * D_ + h * HD_;
#pragma unroll
        for (int dt = 0; dt < 8; ++dt) {
            const int cc = dt * 8 + 2 * tig;
            *reinterpret_cast<float2*>(out0 + cc) =
                make_float2(oc[mt][dt][0] * inv0, oc[mt][dt][1] * inv0);
            *reinterpret_cast<float2*>(out1 + cc) =
                make_float2(oc[mt][dt][2] * inv1, oc[mt][dt][3] * inv1);
        }
    }
}

// ---------------------------------------------------------------------------
extern "C" void kernel_launch(void* const* d_in, const int* in_sizes, int n_in,
                              void* d_out, int out_size) {
    const float* x = nullptr;
    const float* w_qkv = nullptr;
    const float* w_out = nullptr;
    for (int i = 0; i < n_in; ++i) {
        if (in_sizes[i] == M_ * D_)       x = (const float*)d_in[i];
        else if (in_sizes[i] == N3_ * D_) w_qkv = (const float*)d_in[i];
        else if (in_sizes[i] == D_ * D_)  w_out = (const float*)d_in[i];
    }
    float* out = (float*)d_out;

    static bool attr_set = false;
    if (!attr_set) {
        cudaFuncSetAttribute(gemm_qkv_kernel,
                             cudaFuncAttributeMaxDynamicSharedMemorySize, GEMM_SMEM);
        cudaFuncSetAttribute(gemm_out_kernel,
                             cudaFuncAttributeMaxDynamicSharedMemorySize, GEMM_SMEM);
        attr_set = true;
    }

    gemm_qkv_kernel<<<dim3(N3_ / 128, M_ / 128), 256, GEMM_SMEM>>>(x, w_qkv);
    // 512 blocks (16 bh x 32 q-tiles), 128 threads, 2 CTAs/SM
    flash_f16_kernel<<<dim3(B_ * H_, T_ / 128), 128>>>();
    gemm_out_kernel<<<dim3(D_ / 128, M_ / 128), 256, GEMM_SMEM>>>(w_out, out);
}

// round 14
// speedup vs baseline: 2.2421x; 1.1071x over previous
#include <cuda_runtime.h>
#include <cuda_fp16.h>
#include <cstdint>

#define B_   2
#define T_   4096
#define D_   512
#define H_   8
#define HD_  64
#define M_   (B_ * T_)
#define N3_  (3 * D_)

// f16 scratch (aligned for 16B vector access)
__device__ __align__(256) __half g_hx[M_ * D_];     // x in f16
__device__ __align__(256) __half g_hwq[N3_ * D_];   // w_qkv in f16
__device__ __align__(256) __half g_hwo[D_ * D_];    // w_out in f16
__device__ __align__(256) __half g_qkvh[M_ * N3_];  // qkv (Q pre-scaled) f16
__device__ __align__(256) __half g_atth[M_ * D_];   // attention out f16

#define QSCALE 0.180336879f   /* 0.125 * log2(e) */

// ---------------------------------------------------------------------------
// helpers
// ---------------------------------------------------------------------------
__device__ __forceinline__ unsigned cvt_h2(float lo, float hi) {
    unsigned r;
    asm("cvt.rn.f16x2.f32 %0, %1, %2;" : "=r"(r) : "f"(hi), "f"(lo));
    return r;
}
__device__ __forceinline__ float ex2(float x) {
    float r;
    asm("ex2.approx.ftz.f32 %0, %1;" : "=f"(r) : "f"(x));
    return r;
}
__device__ __forceinline__ void mma_f16(float d[4], const unsigned a[4],
                                        const unsigned b[2]) {
    asm volatile(
        "mma.sync.aligned.m16n8k16.row.col.f32.f16.f16.f32 "
        "{%0,%1,%2,%3}, {%4,%5,%6,%7}, {%8,%9}, {%0,%1,%2,%3};\n"
        : "+f"(d[0]), "+f"(d[1]), "+f"(d[2]), "+f"(d[3])
        : "r"(a[0]), "r"(a[1]), "r"(a[2]), "r"(a[3]), "r"(b[0]), "r"(b[1]));
}
__device__ __forceinline__ uint32_t smem_u32(const void* p) {
    uint32_t a;
    asm("{ .reg .u64 t; cvta.to.shared.u64 t, %1; cvt.u32.u64 %0, t; }"
        : "=r"(a) : "l"(p));
    return a;
}
__device__ __forceinline__ void cp16(uint32_t dst, const void* src) {
    asm volatile("cp.async.cg.shared.global [%0], [%1], 16;"
                 :: "r"(dst), "l"(src) : "memory");
}
#define CP_COMMIT() asm volatile("cp.async.commit_group;" ::: "memory")
#define CP_WAIT1()  asm volatile("cp.async.wait_group 1;" ::: "memory")
#define CP_WAIT0()  asm volatile("cp.async.wait_group 0;" ::: "memory")

// ---------------------------------------------------------------------------
// fp32 -> f16 convert (grid-stride, float4 -> 2x half2)
// ---------------------------------------------------------------------------
__global__ void cvt_f2h_kernel(const float* __restrict__ src,
                               __half* __restrict__ dst, int n4) {
    const int stride = gridDim.x * blockDim.x;
    for (int i = blockIdx.x * blockDim.x + threadIdx.x; i < n4; i += stride) {
        const float4 v = reinterpret_cast<const float4*>(src)[i];
        unsigned* p = reinterpret_cast<unsigned*>(dst) + 2 * i;
        p[0] = cvt_h2(v.x, v.y);
        p[1] = cvt_h2(v.z, v.w);
    }
}

// ---------------------------------------------------------------------------
// NT GEMM, f16 in/out of gmem, cp.async 2-stage, BK=64, 64 mmas/iter.
// BM=128, BN=128, 8 warps (4x2), warp tile 32x64.
// smem: half rows, stride 72 halfs (144B): LDS.32 fragments conflict-free.
// ---------------------------------------------------------------------------
#define GST2   72                     // halfs per smem row
#define GA_H   (128 * GST2)           // halfs per tile buffer
#define GBUF_H (2 * GA_H)             // halfs per stage (A+B)
#define GEMM_SMEM (2 * GBUF_H * 2)    // 73728 B

__device__ __forceinline__ void gemm_cp_tile_h(uint32_t sbase, int s,
                                               const __half* __restrict__ A,
                                               const __half* __restrict__ Bm,
                                               int m0, int n0, int K, int k0,
                                               int lr, int c) {
    const uint32_t da = sbase + (uint32_t)(s * GBUF_H + lr * GST2 + c * 8) * 2u;
    const uint32_t db = da + (uint32_t)GA_H * 2u;
#pragma unroll
    for (int i = 0; i < 4; ++i) {
        cp16(da + (uint32_t)(i * 32 * GST2) * 2u,
             A + (size_t)(m0 + lr + 32 * i) * K + k0 + c * 8);
        cp16(db + (uint32_t)(i * 32 * GST2) * 2u,
             Bm + (size_t)(n0 + lr + 32 * i) * K + k0 + c * 8);
    }
    CP_COMMIT();
}

template <bool HALF_OUT, bool SCALEQ>
__device__ __forceinline__ void gemm_nt_h16(const __half* __restrict__ A,
                                            const __half* __restrict__ Bm,
                                            void* __restrict__ Cv,
                                            int N, int K) {
    extern __shared__ __half hs[];
    const uint32_t sbase = smem_u32(hs);

    const int tid = threadIdx.x;
    const int w = tid >> 5;
    const int lane = tid & 31;
    const int gid = lane >> 2;
    const int tig = lane & 3;
    const int wm = w >> 1;            // 0..3 -> 32 rows
    const int wn = w & 1;             // 0..1 -> 64 cols

    const int m0 = blockIdx.y * 128;
    const int n0 = blockIdx.x * 128;

    const int lr = tid >> 3;          // 0..31
    const int c = tid & 7;            // 16B chunk (8 halfs) in 128B k-row

    const int niter = K / 64;         // 8

    gemm_cp_tile_h(sbase, 0, A, Bm, m0, n0, K, 0, lr, c);
    gemm_cp_tile_h(sbase, 1, A, Bm, m0, n0, K, 64, lr, c);

    float acc[2][8][4] = {};

#pragma unroll 1
    for (int it = 0; it < niter; ++it) {
        const int s = it & 1;
        if (it + 1 < niter) { CP_WAIT1(); } else { CP_WAIT0(); }
        __syncthreads();

        const __half* As = hs + s * GBUF_H;
        const __half* Bs = As + GA_H;

#pragma unroll
        for (int ks = 0; ks < 4; ++ks) {
            unsigned aa[2][4], bb[8][2];
#pragma unroll
            for (int mt = 0; mt < 2; ++mt) {
                const int row = wm * 32 + mt * 16 + gid;
                const __half* p = As + row * GST2 + ks * 16 + 2 * tig;
                aa[mt][0] = *reinterpret_cast<const unsigned*>(p);
                aa[mt][1] = *reinterpret_cast<const unsigned*>(p + 8 * GST2);
                aa[mt][2] = *reinterpret_cast<const unsigned*>(p + 8);
                aa[mt][3] = *reinterpret_cast<const unsigned*>(p + 8 * GST2 + 8);
            }
#pragma unroll
            for (int nt = 0; nt < 8; ++nt) {
                const __half* p = Bs + (wn * 64 + nt * 8 + gid) * GST2 + ks * 16 + 2 * tig;
                bb[nt][0] = *reinterpret_cast<const unsigned*>(p);
                bb[nt][1] = *reinterpret_cast<const unsigned*>(p + 8);
            }
#pragma unroll
            for (int mt = 0; mt < 2; ++mt)
#pragma unroll
                for (int nt = 0; nt < 8; ++nt)
                    mma_f16(acc[mt][nt], aa[mt], bb[nt]);
        }

        __syncthreads();
        if (it + 2 < niter)
            gemm_cp_tile_h(sbase, s, A, Bm, m0, n0, K, (it + 2) * 64, lr, c);
    }

#pragma unroll
    for (int mt = 0; mt < 2; ++mt) {
        const int r0 = m0 + wm * 32 + mt * 16 + gid;
#pragma unroll
        for (int nt = 0; nt < 8; ++nt) {
            const int cc = n0 + wn * 64 + nt * 8 + 2 * tig;
            if (HALF_OUT) {
                __half* Ch = reinterpret_cast<__half*>(Cv);
                const float sq = (SCALEQ && cc < 512) ? QSCALE : 1.0f;
                *reinterpret_cast<unsigned*>(Ch + (size_t)r0 * N + cc) =
                    cvt_h2(acc[mt][nt][0] * sq, acc[mt][nt][1] * sq);
                *reinterpret_cast<unsigned*>(Ch + (size_t)(r0 + 8) * N + cc) =
                    cvt_h2(acc[mt][nt][2] * sq, acc[mt][nt][3] * sq);
            } else {
                float* Cf = reinterpret_cast<float*>(Cv);
                *reinterpret_cast<float2*>(Cf + (size_t)r0 * N + cc) =
                    make_float2(acc[mt][nt][0], acc[mt][nt][1]);
                *reinterpret_cast<float2*>(Cf + (size_t)(r0 + 8) * N + cc) =
                    make_float2(acc[mt][nt][2], acc[mt][nt][3]);
            }
        }
    }
}

__global__ void __launch_bounds__(256)
gemm_qkv_kernel() {
    gemm_nt_h16<true, true>(g_hx, g_hwq, g_qkvh, N3_, D_);
}

__global__ void __launch_bounds__(256)
gemm_out_kernel(float* __restrict__ out) {
    gemm_nt_h16<false, false>(g_atth, g_hwo, out, D_, D_);
}

// ---------------------------------------------------------------------------
// Flash attention (causal), f16 mma — R11 structure, f16 gmem in/out.
// 128 threads = 4 warps x 32 q-rows, BM=128, BN=64, occ 2.
// Q arrives pre-scaled (log2 domain) from the qkv epilogue.
// ---------------------------------------------------------------------------
#define QST 40            // half2 stride for Q/K rows
#define VSTW 36           // V row stride in words (72 halfs = 144B)

__global__ void __launch_bounds__(128, 2) flash_f16_kernel() {
    __shared__ unsigned Qs[128 * QST];
    __shared__ unsigned Ks[64 * QST];
    __shared__ unsigned Vs[64 * VSTW];

    const int tid = threadIdx.x;
    const int w = tid >> 5;                // 0..3
    const int lane = tid & 31;
    const int gid = lane >> 2;
    const int tig = lane & 3;

    const int qt = (int)gridDim.y - 1 - (int)blockIdx.y;   // heavy tiles first
    const int q0 = qt * 128;
    const int bh = blockIdx.x;
    const int b = bh >> 3;
    const int h = bh & 7;

    const __half* qptr = g_qkvh + (size_t)b * T_ * N3_ + h * HD_;
    const __half* kptr = qptr + D_;
    const __half* vptr = qptr + 2 * D_;

    const int lr = tid >> 3;          // 0..15
    const int c = tid & 7;            // 8-half d-chunk
    const int pb = 8 * (c >> 1) + (c & 1);   // interleave base (slots pb,+2,+4,+6)

    // ---- stage Q (pure permuted copy; already scaled f16) ----
#pragma unroll
    for (int i = 0; i < 8; ++i) {
        const int rr = lr + 16 * i;
        const uint4 v = *reinterpret_cast<const uint4*>(
            qptr + (size_t)(q0 + rr) * N3_ + c * 8);
        unsigned* p = Qs + rr * QST + pb;
        p[0] = v.x; p[2] = v.y; p[4] = v.z; p[6] = v.w;
    }

    // ---- preload first K/V tile ----
    uint4 kreg[4], vreg[4];
#pragma unroll
    for (int i = 0; i < 4; ++i) {
        kreg[i] = *reinterpret_cast<const uint4*>(kptr + (size_t)(lr + 16 * i) * N3_ + c * 8);
        vreg[i] = *reinterpret_cast<const uint4*>(vptr + (size_t)(lr + 16 * i) * N3_ + c * 8);
    }

    float oc[2][8][4] = {};
    float li[2][2] = {};

    const int rowlo = q0 + w * 32;       // warp's lowest q row
    const int niter = 2 * (qt + 1);

    const uint32_t vbase = smem_u32(Vs) + (uint32_t)(lane & 15) * 144u +
                           (uint32_t)((lane >> 4) & 1) * 16u;

    for (int it = 0; it < niter; ++it) {
        const int j0 = it * 64;
        __syncthreads();
        // store K interleaved, V plain row-major
#pragma unroll
        for (int i = 0; i < 4; ++i) {
            const int rr = lr + 16 * i;
            unsigned* pk = Ks + rr * QST + pb;
            pk[0] = kreg[i].x; pk[2] = kreg[i].y;
            pk[4] = kreg[i].z; pk[6] = kreg[i].w;
            *reinterpret_cast<uint4*>(Vs + rr * VSTW + c * 4) = vreg[i];
        }
        __syncthreads();

        if (it + 1 < niter) {
            const int jn = j0 + 64;
#pragma unroll
            for (int i = 0; i < 4; ++i) {
                kreg[i] = *reinterpret_cast<const uint4*>(
                    kptr + (size_t)(jn + lr + 16 * i) * N3_ + c * 8);
                vreg[i] = *reinterpret_cast<const uint4*>(
                    vptr + (size_t)(jn + lr + 16 * i) * N3_ + c * 8);
            }
        }

        if (j0 > rowlo + 31) continue;   // warp fully masked this iter

        // ---- S = Q K^T  (4 k-chunks of 16) ----
        float sc[2][8][4] = {};
#pragma unroll
        for (int ks = 0; ks < 4; ++ks) {
            unsigned qa[2][4];
#pragma unroll
            for (int mt = 0; mt < 2; ++mt) {
                const int row = w * 32 + mt * 16 + gid;
                const uint2 lo = *reinterpret_cast<const uint2*>(
                    Qs + row * QST + ks * 8 + 2 * tig);
                const uint2 hi = *reinterpret_cast<const uint2*>(
                    Qs + (row + 8) * QST + ks * 8 + 2 * tig);
                qa[mt][0] = lo.x; qa[mt][1] = hi.x;
                qa[mt][2] = lo.y; qa[mt][3] = hi.y;
            }
#pragma unroll
            for (int nt = 0; nt < 8; ++nt) {
                const uint2 kb = *reinterpret_cast<const uint2*>(
                    Ks + (nt * 8 + gid) * QST + ks * 8 + 2 * tig);
                unsigned bbr[2] = {kb.x, kb.y};
                mma_f16(sc[0][nt], qa[0], bbr);
                mma_f16(sc[1][nt], qa[1], bbr);
            }
        }

        // ---- causal mask ----
#pragma unroll
        for (int mt = 0; mt < 2; ++mt) {
            const int rbase = rowlo + mt * 16;
            if (j0 + 63 > rbase) {
                const int r0 = rbase + gid, r1 = rbase + gid + 8;
#pragma unroll
                for (int nt = 0; nt < 8; ++nt) {
                    const int cc = j0 + nt * 8 + 2 * tig;
                    if (cc > r0)     sc[mt][nt][0] = -1e30f;
                    if (cc + 1 > r0) sc[mt][nt][1] = -1e30f;
                    if (cc > r1)     sc[mt][nt][2] = -1e30f;
                    if (cc + 1 > r1) sc[mt][nt][3] = -1e30f;
                }
            }
        }

        // ---- exp2 + per-lane row sums ----
#pragma unroll
        for (int mt = 0; mt < 2; ++mt) {
            float s0 = 0.0f, s1 = 0.0f;
#pragma unroll
            for (int nt = 0; nt < 8; ++nt) {
                sc[mt][nt][0] = ex2(sc[mt][nt][0]);
                sc[mt][nt][1] = ex2(sc[mt][nt][1]);
                sc[mt][nt][2] = ex2(sc[mt][nt][2]);
                sc[mt][nt][3] = ex2(sc[mt][nt][3]);
                s0 += sc[mt][nt][0] + sc[mt][nt][1];
                s1 += sc[mt][nt][2] + sc[mt][nt][3];
            }
            li[mt][0] += s0;
            li[mt][1] += s1;
        }

        // ---- P fragments: pure cvt ----
        unsigned pa[2][4][4];
#pragma unroll
        for (int mt = 0; mt < 2; ++mt)
#pragma unroll
            for (int ks = 0; ks < 4; ++ks) {
                pa[mt][ks][0] = cvt_h2(sc[mt][2 * ks][0], sc[mt][2 * ks][1]);
                pa[mt][ks][1] = cvt_h2(sc[mt][2 * ks][2], sc[mt][2 * ks][3]);
                pa[mt][ks][2] = cvt_h2(sc[mt][2 * ks + 1][0], sc[mt][2 * ks + 1][1]);
                pa[mt][ks][3] = cvt_h2(sc[mt][2 * ks + 1][2], sc[mt][2 * ks + 1][3]);
            }

        // ---- O += P V  (V^T via ldmatrix.x4.trans) ----
#pragma unroll
        for (int dtp = 0; dtp < 4; ++dtp) {
#pragma unroll
            for (int ks = 0; ks < 4; ++ks) {
                unsigned r0, r1, r2, r3;
                asm volatile(
                    "ldmatrix.sync.aligned.m8n8.x4.trans.shared.b16 "
                    "{%0,%1,%2,%3}, [%4];"
                    : "=r"(r0), "=r"(r1), "=r"(r2), "=r"(r3)
                    : "r"(vbase + (uint32_t)ks * 2304u + (uint32_t)dtp * 32u));
                unsigned vb0[2] = {r0, r1};
                unsigned vb1[2] = {r2, r3};
                mma_f16(oc[0][2 * dtp],     pa[0][ks], vb0);
                mma_f16(oc[1][2 * dtp],     pa[1][ks], vb0);
                mma_f16(oc[0][2 * dtp + 1], pa[0][ks], vb1);
                mma_f16(oc[1][2 * dtp + 1], pa[1][ks], vb1);
            }
        }
    }

    // ---- epilogue: quad-reduce row sums, normalize, store f16 ----
#pragma unroll
    for (int mt = 0; mt < 2; ++mt) {
        float s0 = li[mt][0], s1 = li[mt][1];
        s0 += __shfl_xor_sync(0xffffffffu, s0, 1);
        s0 += __shfl_xor_sync(0xffffffffu, s0, 2);
        s1 += __shfl_xor_sync(0xffffffffu, s1, 1);
        s1 += __shfl_xor_sync(0xffffffffu, s1, 2);
        const float inv0 = 1.0f / s0;
        const float inv1 = 1.0f / s1;
        const int r0 = q0 + w * 32 + mt * 16 + gid;
        __half* out0 = g_atth + ((size_t)(b * T_ + r0)) * D_ + h * HD_;
        __half* out1 = g_atth + ((size_t)(b * T_ + r0 + 8)) * D_ + h * HD_;
#pragma unroll
        for (int dt = 0; dt < 8; ++dt) {
            const int cc = dt * 8 + 2 * tig;
            *reinterpret_cast<unsigned*>(out0 + cc) =
                cvt_h2(oc[mt][dt][0] * inv0, oc[mt][dt][1] * inv0);
            *reinterpret_cast<unsigned*>(out1 + cc) =
                cvt_h2(oc[mt][dt][2] * inv1, oc[mt][dt][3] * inv1);
        }
    }
}

// ---------------------------------------------------------------------------
extern "C" void kernel_launch(void* const* d_in, const int* in_sizes, int n_in,
                              void* d_out, int out_size) {
    const float* x = nullptr;
    const float* w_qkv = nullptr;
    const float* w_out = nullptr;
    for (int i = 0; i < n_in; ++i) {
        if (in_sizes[i] == M_ * D_)       x = (const float*)d_in[i];
        else if (in_sizes[i] == N3_ * D_) w_qkv = (const float*)d_in[i];
        else if (in_sizes[i] == D_ * D_)  w_out = (const float*)d_in[i];
    }
    float* out = (float*)d_out;

    static __half *hx = nullptr, *hwq = nullptr, *hwo = nullptr;
    static bool attr_set = false;
    if (!attr_set) {
        cudaFuncSetAttribute(gemm_qkv_kernel,
                             cudaFuncAttributeMaxDynamicSharedMemorySize, GEMM_SMEM);
        cudaFuncSetAttribute(gemm_out_kernel,
                             cudaFuncAttributeMaxDynamicSharedMemorySize, GEMM_SMEM);
        cudaGetSymbolAddress((void**)&hx, g_hx);
        cudaGetSymbolAddress((void**)&hwq, g_hwq);
        cudaGetSymbolAddress((void**)&hwo, g_hwo);
        attr_set = true;
    }

    // 1) fp32 -> f16 converts
    cvt_f2h_kernel<<<1024, 256>>>(x, hx, (M_ * D_) / 4);
    cvt_f2h_kernel<<<512, 256>>>(w_qkv, hwq, (N3_ * D_) / 4);
    cvt_f2h_kernel<<<256, 256>>>(w_out, hwo, (D_ * D_) / 4);

    // 2) QKV projection (f16 in, f16 out, Q pre-scaled)
    gemm_qkv_kernel<<<dim3(N3_ / 128, M_ / 128), 256, GEMM_SMEM>>>();

    // 3) Flash attention (f16 end-to-end)
    flash_f16_kernel<<<dim3(B_ * H_, T_ / 128), 128>>>();

    // 4) Output projection (f16 in, f32 out)
    gemm_out_kernel<<<dim3(D_ / 128, M_ / 128), 256, GEMM_SMEM>>>(out);
}